// round 14
// baseline (speedup 1.0000x reference)
#include <cuda_runtime.h>
#include <cuda_fp16.h>
#include <math.h>
#include <stdint.h>

// ---------------------------------------------------------------------------
// AttnBlock via mma.sync HMMA (base sm_100 target).
// Single-pass fp16 GEMMs, fp32 accum.
// R14: algebraic fusion — since softmax rows sum to 1:
//   out = P.(t.(Wo.Wv)^T) + (Wo.bv + bo), so the output projection GEMM
// stage is eliminated; PV writes the final transposed+residual output.
// Wvo = Wo.Wv precomputed by a tiny GEMM; b' = Wo.bv + bo by a matvec.
// ---------------------------------------------------------------------------

#define BB   32
#define CC   512
#define SS   1024
#define NGRP 32
#define CPG  16
#define SCALE_QK 0.044194173824159216f

typedef __half fp16;

// ------------------------------- scratch ----------------------------------
static __device__ fp16 g_th [(size_t)BB * SS * CC];
static __device__ fp16 g_qh [(size_t)BB * SS * CC];
static __device__ fp16 g_kh [(size_t)BB * SS * CC];
static __device__ fp16 g_vth[(size_t)BB * CC * SS];   // v' transposed [B,C,S]
static __device__ fp16 g_sc [(size_t)BB * SS * SS];   // fp16 scores
static __device__ fp16 g_ph [(size_t)BB * SS * SS];
static __device__ fp16 g_wh [4 * CC * CC];            // Wq, Wk, Wv, Wo (fp16)
static __device__ fp16 g_wvt[CC * CC];                // Wv^T fp16
static __device__ fp16 g_wvo[CC * CC];                // Wvo = Wo.Wv fp16
static __device__ float g_bp [CC];                    // b' = Wo.bv + bo

// ------------------------------ asm helpers --------------------------------
__device__ __forceinline__ uint32_t smem_u32(const void* p) {
    uint32_t a;
    asm("{ .reg .u64 t; cvta.to.shared.u64 t, %1; cvt.u32.u64 %0, t; }" : "=r"(a) : "l"(p));
    return a;
}
#define CP16(dst, src) \
    asm volatile("cp.async.cg.shared.global [%0], [%1], 16;" :: "r"(dst), "l"(src))
#define CP_COMMIT() asm volatile("cp.async.commit_group;" ::: "memory")
#define CP_WAIT(n)  asm volatile("cp.async.wait_group %0;" :: "n"(n) : "memory")

#define LDSM4(r0, r1, r2, r3, addr) \
    asm volatile("ldmatrix.sync.aligned.m8n8.x4.shared.b16 {%0,%1,%2,%3}, [%4];" \
        : "=r"(r0), "=r"(r1), "=r"(r2), "=r"(r3) : "r"(addr))

#define MMA_FP16(d, a, b) \
    asm volatile("mma.sync.aligned.m16n8k16.row.col.f32.f16.f16.f32 " \
        "{%0,%1,%2,%3}, {%4,%5,%6,%7}, {%8,%9}, {%0,%1,%2,%3};" \
        : "+f"((d)[0]), "+f"((d)[1]), "+f"((d)[2]), "+f"((d)[3]) \
        : "r"((a)[0]), "r"((a)[1]), "r"((a)[2]), "r"((a)[3]), \
          "r"((b)[0]), "r"((b)[1]))

#define STAGE_B 20480

// ---------------------------------------------------------------------------
// Shared GEMM mainloop (128x128 tile, BK=32, 8 warps 4x2, 4-stage cp.async,
// single barrier/chunk, 2 CTAs/SM). Produces acc[2][8][4].
// ---------------------------------------------------------------------------
#define GEMM_MAINLOOP(Aptr, Bptr, bm_, bn_, lda_, ldb_, Kval)                 \
    const uint32_t sb = smem_u32(smem);                                       \
    const int tid = threadIdx.x, wid = tid >> 5, lane = tid & 31;             \
    const int lrow = tid >> 2, lseg = tid & 3;                                \
    float acc[2][8][4];                                                       \
    _Pragma("unroll")                                                         \
    for (int i = 0; i < 2; i++)                                               \
        _Pragma("unroll")                                                     \
        for (int j = 0; j < 8; j++)                                           \
            _Pragma("unroll")                                                 \
            for (int t = 0; t < 4; t++) acc[i][j][t] = 0.f;                   \
    auto load_stage = [&](int k0, int buf) {                                  \
        const uint32_t base = sb + buf * STAGE_B;                             \
        _Pragma("unroll")                                                     \
        for (int half = 0; half < 2; half++) {                                \
            const int r = lrow + half * 64;                                   \
            const uint32_t doff = (uint32_t)(r * 80 + lseg * 16);             \
            CP16(base +         doff, (Aptr) + (size_t)((bm_) + r) * (lda_) + k0 + lseg * 8); \
            CP16(base + 10240 + doff, (Bptr) + (size_t)((bn_) + r) * (ldb_) + k0 + lseg * 8); \
        }                                                                     \
    };                                                                        \
    const int m0 = (wid & 3) * 32, n0 = (wid >> 2) * 64;                      \
    const int arow = (lane & 7) + ((lane >> 3) & 1) * 8;                      \
    const int acol = (lane >> 4) * 8;                                         \
    const int brow = (lane & 7) + (lane >> 4) * 8;                            \
    const int bcol = ((lane >> 3) & 1) * 8;                                   \
    const int NC = (Kval) >> 5;                                               \
    load_stage(0, 0);  CP_COMMIT();                                           \
    load_stage(32, 1); CP_COMMIT();                                           \
    load_stage(64, 2); CP_COMMIT();                                           \
    for (int c = 0; c < NC; c++) {                                            \
        const int rem = NC - 1 - c;                                           \
        if (rem >= 2)      { CP_WAIT(2); }                                    \
        else if (rem == 1) { CP_WAIT(1); }                                    \
        else               { CP_WAIT(0); }                                    \
        __syncthreads();                                                      \
        if (c + 3 < NC) { load_stage((c + 3) << 5, (c + 3) & 3); CP_COMMIT(); } \
        const uint32_t st = sb + (c & 3) * STAGE_B;                           \
        _Pragma("unroll")                                                     \
        for (int kx = 0; kx < 32; kx += 16) {                                 \
            uint32_t fa[2][4];                                                \
            uint32_t fb[8][2];                                                \
            _Pragma("unroll")                                                 \
            for (int mt = 0; mt < 2; mt++) {                                  \
                const uint32_t ad = st +                                      \
                    (uint32_t)(((m0 + mt * 16 + arow) * 40 + kx + acol) * 2); \
                LDSM4(fa[mt][0], fa[mt][1], fa[mt][2], fa[mt][3], ad);        \
            }                                                                 \
            _Pragma("unroll")                                                 \
            for (int p = 0; p < 4; p++) {                                     \
                const uint32_t bd = st + 10240 +                              \
                    (uint32_t)(((n0 + p * 16 + brow) * 40 + kx + bcol) * 2);  \
                LDSM4(fb[2*p][0], fb[2*p][1], fb[2*p+1][0], fb[2*p+1][1], bd);\
            }                                                                 \
            _Pragma("unroll")                                                 \
            for (int mt = 0; mt < 2; mt++)                                    \
                _Pragma("unroll")                                             \
                for (int nt = 0; nt < 8; nt++)                                \
                    MMA_FP16(acc[mt][nt], fa[mt], fb[nt]);                    \
        }                                                                     \
    }                                                                         \
    __syncthreads();

// Normal fp16 epilogue (C[m,n])
#define EPI_FP16(Ch, bias_, bm_, bn_, ldc_, sC_, alpha_)                      \
    _Pragma("unroll")                                                         \
    for (int mt = 0; mt < 2; mt++) {                                          \
        const int gm = (bm_) + m0 + mt * 16 + (lane >> 2);                    \
        _Pragma("unroll")                                                     \
        for (int nt = 0; nt < 8; nt++) {                                      \
            const int gn = (bn_) + n0 + nt * 8 + 2 * (lane & 3);              \
            const float b0 = (bias_) ? (bias_)[gn]     : 0.f;                 \
            const float b1 = (bias_) ? (bias_)[gn + 1] : 0.f;                 \
            const float* d = acc[mt][nt];                                     \
            const size_t r0 = (size_t)blockIdx.z * (sC_) + (size_t)gm * (ldc_) + gn; \
            const size_t r1 = r0 + (size_t)8 * (ldc_);                        \
            *reinterpret_cast<__half2*>(&(Ch)[r0]) = __halves2half2(          \
                __float2half(d[0] * (alpha_) + b0), __float2half(d[1] * (alpha_) + b1)); \
            *reinterpret_cast<__half2*>(&(Ch)[r1]) = __halves2half2(          \
                __float2half(d[2] * (alpha_) + b0), __float2half(d[3] * (alpha_) + b1)); \
        }                                                                     \
    }

// Transposed epilogue via smem stage: writes C^T[n,m] (fp16) or fp32+resid
#define EPI_TRANS(IS_F32, Ch, Cf, bias_, resid_, bm_, bn_, ldc_, sC_, alpha_) \
    {                                                                         \
    float* smt = reinterpret_cast<float*>(smem);                              \
    const int nhme = wid >> 2;                                                \
    _Pragma("unroll")                                                         \
    for (int nh = 0; nh < 2; nh++) {                                          \
        __syncthreads();                                                      \
        if (nhme == nh) {                                                     \
            _Pragma("unroll")                                                 \
            for (int mt = 0; mt < 2; mt++) {                                  \
                const int sl = m0 + mt * 16 + (lane >> 2);                    \
                _Pragma("unroll")                                             \
                for (int nt = 0; nt < 8; nt++) {                              \
                    const int cl = nt * 8 + 2 * (lane & 3);                   \
                    const float b0 = (bias_) ? (bias_)[(bn_) + nh * 64 + cl]     : 0.f; \
                    const float b1 = (bias_) ? (bias_)[(bn_) + nh * 64 + cl + 1] : 0.f; \
                    const float* d = acc[mt][nt];                             \
                    smt[cl       * 132 + sl]     = d[0] * (alpha_) + b0;      \
                    smt[(cl + 1) * 132 + sl]     = d[1] * (alpha_) + b1;      \
                    smt[cl       * 132 + sl + 8] = d[2] * (alpha_) + b0;      \
                    smt[(cl + 1) * 132 + sl + 8] = d[3] * (alpha_) + b1;      \
                }                                                             \
            }                                                                 \
        }                                                                     \
        __syncthreads();                                                      \
        if (!(IS_F32)) {                                                      \
            _Pragma("unroll")                                                 \
            for (int it = 0; it < 16; it++) {                                 \
                const int idx = tid + it * 256;                               \
                const int cl = idx >> 6, s2 = (idx & 63) * 2;                 \
                const size_t o = (size_t)blockIdx.z * (sC_) +                 \
                    (size_t)((bn_) + nh * 64 + cl) * (ldc_) + (bm_) + s2;     \
                *reinterpret_cast<__half2*>(&(Ch)[o]) = __halves2half2(       \
                    __float2half(smt[cl * 132 + s2]),                         \
                    __float2half(smt[cl * 132 + s2 + 1]));                    \
            }                                                                 \
        } else {                                                              \
            _Pragma("unroll")                                                 \
            for (int it = 0; it < 32; it++) {                                 \
                const int idx = tid + it * 256;                               \
                const int cl = idx >> 7, sl = idx & 127;                      \
                const size_t o = (size_t)blockIdx.z * (sC_) +                 \
                    (size_t)((bn_) + nh * 64 + cl) * (ldc_) + (bm_) + sl;     \
                (Cf)[o] = smt[cl * 132 + sl] + (resid_)[o];                   \
            }                                                                 \
        }                                                                     \
    }                                                                         \
    }

// ---------------------------------------------------------------------------
// Fused QKV: grid.x in [0,12): sel = x>>2 picks Q/K/V', bn = (x&3)*128.
// Q,K -> fp16 [B,S,C]; V' = t.Wvo^T -> transposed fp16 [B,C,S], no bias.
// ---------------------------------------------------------------------------
__global__ void __launch_bounds__(256, 2)
qkv_mma(const fp16* __restrict__ T, const fp16* __restrict__ W,
        const fp16* __restrict__ Wvo,
        const float* __restrict__ bq, const float* __restrict__ bk,
        fp16* __restrict__ Q, fp16* __restrict__ Kout, fp16* __restrict__ VT)
{
    extern __shared__ __align__(16) char smem[];
    const int sel = blockIdx.x >> 2;
    const int bm = blockIdx.y * 128, bn = (blockIdx.x & 3) * 128;
    const fp16* A = T + (size_t)blockIdx.z * SS * CC;
    const fp16* B = (sel < 2) ? (W + (size_t)sel * CC * CC) : Wvo;

    GEMM_MAINLOOP(A, B, bm, bn, CC, CC, CC)

    const long long sSC = (long long)SS * CC;
    if (sel == 0) {
        EPI_FP16(Q, bq, bm, bn, CC, sSC, 1.f)
    } else if (sel == 1) {
        EPI_FP16(Kout, bk, bm, bn, CC, sSC, 1.f)
    } else {
        EPI_TRANS(false, VT, (float*)nullptr, (const float*)nullptr,
                  (const float*)nullptr, bm, bn, SS, sSC, 1.f)
    }
}

// ---------------------------------------------------------------------------
// Generic GEMM, fp16 out (scores with alpha; Wvo prep)
// ---------------------------------------------------------------------------
__global__ void __launch_bounds__(256, 2)
gemm_h(const fp16* __restrict__ Ain, const fp16* __restrict__ Bin,
       const float* __restrict__ bias, fp16* __restrict__ Ch,
       int K, int lda, int ldb, int ldc,
       long long sA, long long sB, long long sC, float alpha)
{
    extern __shared__ __align__(16) char smem[];
    const int bm = blockIdx.y * 128, bn = blockIdx.x * 128;
    const fp16* A = Ain + (size_t)blockIdx.z * sA;
    const fp16* B = Bin + (size_t)blockIdx.z * sB;

    GEMM_MAINLOOP(A, B, bm, bn, lda, ldb, K)
    EPI_FP16(Ch, bias, bm, bn, ldc, sC, alpha)
}

// ---------------------------------------------------------------------------
// Final PV GEMM: out[b,c,s] = (P . v')[s,c] + b'[c] + x[b,c,s]
// ---------------------------------------------------------------------------
__global__ void __launch_bounds__(256, 2)
gemm_pv_final(const fp16* __restrict__ P, const fp16* __restrict__ VT,
              const float* __restrict__ bp, const float* __restrict__ X,
              float* __restrict__ Out)
{
    extern __shared__ __align__(16) char smem[];
    const int bm = blockIdx.y * 128, bn = blockIdx.x * 128;
    const fp16* A = P  + (size_t)blockIdx.z * SS * SS;
    const fp16* B = VT + (size_t)blockIdx.z * CC * SS;

    GEMM_MAINLOOP(A, B, bm, bn, SS, SS, SS)

    const long long sCS = (long long)CC * SS;
    EPI_TRANS(true, (fp16*)nullptr, Out, bp, X, bm, bn, SS, sCS, 1.f)
}

// ---------------------------------------------------------------------------
// Fused GroupNorm: one block per (b,g); 1024 threads (one per s), 16 c each.
// ---------------------------------------------------------------------------
__global__ __launch_bounds__(1024)
void gn_fused_kernel(const float* __restrict__ x, const float* __restrict__ w,
                     const float* __restrict__ bgn, fp16* __restrict__ th)
{
    const int b = blockIdx.x >> 5, g = blockIdx.x & 31;
    const size_t base = ((size_t)b * CC + (size_t)g * CPG) * SS;
    const int t = threadIdx.x;

    float v[CPG];
    float s = 0.f, s2 = 0.f;
    #pragma unroll
    for (int c = 0; c < CPG; c++) {
        v[c] = x[base + (size_t)c * SS + t];
        s += v[c]; s2 += v[c] * v[c];
    }
    #pragma unroll
    for (int o = 16; o; o >>= 1) {
        s  += __shfl_xor_sync(0xffffffffu, s, o);
        s2 += __shfl_xor_sync(0xffffffffu, s2, o);
    }
    __shared__ float ws[32], ws2[32];
    __shared__ float s_mu, s_inv;
    const int lane = t & 31, wrp = t >> 5;
    if (lane == 0) { ws[wrp] = s; ws2[wrp] = s2; }
    __syncthreads();
    if (wrp == 0) {
        float a = ws[lane], a2 = ws2[lane];
        #pragma unroll
        for (int o = 16; o; o >>= 1) {
            a  += __shfl_xor_sync(0xffffffffu, a, o);
            a2 += __shfl_xor_sync(0xffffffffu, a2, o);
        }
        if (lane == 0) {
            const float inv_n = 1.f / (CPG * SS);
            const float mu = a * inv_n;
            s_mu = mu;
            s_inv = rsqrtf(a2 * inv_n - mu * mu + 1e-6f);
        }
    }
    __syncthreads();
    const float mu = s_mu, inv = s_inv;

    __half2 o8[CPG / 2];
    #pragma unroll
    for (int c = 0; c < CPG; c += 2) {
        const int cc0 = g * CPG + c;
        o8[c / 2] = __halves2half2(
            __float2half((v[c]     - mu) * inv * w[cc0]     + bgn[cc0]),
            __float2half((v[c + 1] - mu) * inv * w[cc0 + 1] + bgn[cc0 + 1]));
    }
    fp16* dst = th + ((size_t)b * SS + t) * CC + g * CPG;
    reinterpret_cast<uint4*>(dst)[0] = reinterpret_cast<uint4*>(o8)[0];
    reinterpret_cast<uint4*>(dst)[1] = reinterpret_cast<uint4*>(o8)[1];
}

// ---------------------------------------------------------------------------
// Row softmax over 1024 fp16 logits; P -> fp16
// ---------------------------------------------------------------------------
__global__ __launch_bounds__(256)
void softmax_kernel(const fp16* __restrict__ s, fp16* __restrict__ ph)
{
    const size_t ro = (size_t)blockIdx.x * SS;
    const __half2 h0 = reinterpret_cast<const __half2*>(&s[ro])[threadIdx.x * 2];
    const __half2 h1 = reinterpret_cast<const __half2*>(&s[ro])[threadIdx.x * 2 + 1];
    float4 v = make_float4(__low2float(h0), __high2float(h0),
                           __low2float(h1), __high2float(h1));

    float m = fmaxf(fmaxf(v.x, v.y), fmaxf(v.z, v.w));
    #pragma unroll
    for (int o = 16; o; o >>= 1) m = fmaxf(m, __shfl_xor_sync(0xffffffffu, m, o));
    __shared__ float redm[8], reds[8];
    const int lane = threadIdx.x & 31, wid = threadIdx.x >> 5;
    if (lane == 0) redm[wid] = m;
    __syncthreads();
    float M = redm[0];
    #pragma unroll
    for (int i = 1; i < 8; i++) M = fmaxf(M, redm[i]);

    v.x = expf(v.x - M); v.y = expf(v.y - M);
    v.z = expf(v.z - M); v.w = expf(v.w - M);
    float sum = v.x + v.y + v.z + v.w;
    #pragma unroll
    for (int o = 16; o; o >>= 1) sum += __shfl_xor_sync(0xffffffffu, sum, o);
    if (lane == 0) reds[wid] = sum;
    __syncthreads();
    float T = 0.f;
    #pragma unroll
    for (int i = 0; i < 8; i++) T += reds[i];
    const float inv = 1.f / T;

    *reinterpret_cast<__half2*>(&ph[ro + threadIdx.x * 4]) =
        __halves2half2(__float2half(v.x * inv), __float2half(v.y * inv));
    *reinterpret_cast<__half2*>(&ph[ro + threadIdx.x * 4 + 2]) =
        __halves2half2(__float2half(v.z * inv), __float2half(v.w * inv));
}

// ---------------------------------------------------------------------------
// All four weight converts in one launch
// ---------------------------------------------------------------------------
__global__ __launch_bounds__(256)
void wconv4_kernel(const float* __restrict__ a, const float* __restrict__ b,
                   const float* __restrict__ c, const float* __restrict__ d,
                   fp16* __restrict__ dst)
{
    const int n2 = CC * CC / 2;
    for (int i = blockIdx.x * 256 + threadIdx.x; i < n2; i += gridDim.x * 256) {
        const float2 va = reinterpret_cast<const float2*>(a)[i];
        const float2 vb = reinterpret_cast<const float2*>(b)[i];
        const float2 vc = reinterpret_cast<const float2*>(c)[i];
        const float2 vd = reinterpret_cast<const float2*>(d)[i];
        reinterpret_cast<__half2*>(dst)[i]          = __floats2half2_rn(va.x, va.y);
        reinterpret_cast<__half2*>(dst)[n2 + i]     = __floats2half2_rn(vb.x, vb.y);
        reinterpret_cast<__half2*>(dst)[2 * n2 + i] = __floats2half2_rn(vc.x, vc.y);
        reinterpret_cast<__half2*>(dst)[3 * n2 + i] = __floats2half2_rn(vd.x, vd.y);
    }
}

// ---------------------------------------------------------------------------
// Wv fp16 [C,C] -> Wv^T fp16 (32x32 smem tiles)
// ---------------------------------------------------------------------------
__global__ __launch_bounds__(256)
void wtrans_kernel(const fp16* __restrict__ src, fp16* __restrict__ dst)
{
    __shared__ fp16 t[32][33];
    const int r0 = blockIdx.y * 32, c0 = blockIdx.x * 32;
    const int tx = threadIdx.x, ty = threadIdx.y;
    #pragma unroll
    for (int i = ty; i < 32; i += 8)
        t[i][tx] = src[(size_t)(r0 + i) * CC + c0 + tx];
    __syncthreads();
    #pragma unroll
    for (int i = ty; i < 32; i += 8)
        dst[(size_t)(c0 + i) * CC + r0 + tx] = t[tx][i];
}

// ---------------------------------------------------------------------------
// b'[c] = dot(Wo[c,:], bv) + bo[c]
// ---------------------------------------------------------------------------
__global__ __launch_bounds__(256)
void bvec_kernel(const float* __restrict__ Wo, const float* __restrict__ bv,
                 const float* __restrict__ bo, float* __restrict__ bp)
{
    const int c = blockIdx.x * 256 + threadIdx.x;
    if (c < CC) {
        float a = 0.f;
        for (int j = 0; j < CC; j++) a += Wo[(size_t)c * CC + j] * bv[j];
        bp[c] = a + bo[c];
    }
}

// ---------------------------------------------------------------------------
// Launch
// ---------------------------------------------------------------------------
extern "C" void kernel_launch(void* const* d_in, const int* in_sizes, int n_in,
                              void* d_out, int out_size)
{
    const float* x   = (const float*)d_in[0];
    const float* gnw = (const float*)d_in[1];
    const float* gnb = (const float*)d_in[2];
    const float* Wq  = (const float*)d_in[3];
    const float* bq  = (const float*)d_in[4];
    const float* Wk  = (const float*)d_in[5];
    const float* bk  = (const float*)d_in[6];
    const float* Wv  = (const float*)d_in[7];
    const float* bv  = (const float*)d_in[8];
    const float* Wo  = (const float*)d_in[9];
    const float* bo  = (const float*)d_in[10];
    float* out = (float*)d_out;

    fp16 *th, *qh, *kh, *vth, *sc, *ph, *wh, *wvt, *wvo;
    float *bp;
    cudaGetSymbolAddress((void**)&th,  g_th);
    cudaGetSymbolAddress((void**)&qh,  g_qh);
    cudaGetSymbolAddress((void**)&kh,  g_kh);
    cudaGetSymbolAddress((void**)&vth, g_vth);
    cudaGetSymbolAddress((void**)&sc,  g_sc);
    cudaGetSymbolAddress((void**)&ph,  g_ph);
    cudaGetSymbolAddress((void**)&wh,  g_wh);
    cudaGetSymbolAddress((void**)&wvt, g_wvt);
    cudaGetSymbolAddress((void**)&wvo, g_wvo);
    cudaGetSymbolAddress((void**)&bp,  g_bp);

    const int SMEM = 4 * STAGE_B;   // 81920 B
    cudaFuncSetAttribute(qkv_mma,       cudaFuncAttributeMaxDynamicSharedMemorySize, SMEM);
    cudaFuncSetAttribute(gemm_h,        cudaFuncAttributeMaxDynamicSharedMemorySize, SMEM);
    cudaFuncSetAttribute(gemm_pv_final, cudaFuncAttributeMaxDynamicSharedMemorySize, SMEM);

    const long long sSC = (long long)SS * CC;
    const long long sSS = (long long)SS * SS;

    // 0) weight preps: fp16 converts; Wv^T; Wvo = Wo.Wv; b' = Wo.bv + bo
    wconv4_kernel<<<256, 256>>>(Wq, Wk, Wv, Wo, wh);
    wtrans_kernel<<<dim3(16, 16), dim3(32, 8)>>>(wh + 2 * CC * CC, wvt);
    // Wvo[c,k] = Wo[c,:] . WvT[k,:]  (A = Wo fp16, B = Wv^T fp16)
    gemm_h<<<dim3(4, 4, 1), 256, SMEM>>>(wh + 3 * CC * CC, wvt, nullptr, wvo,
                                         CC, CC, CC, CC, 0, 0, 0, 1.f);
    bvec_kernel<<<2, 256>>>(Wo, bv, bo, bp);

    // 1) fused GroupNorm -> t [B,S,C] fp16
    gn_fused_kernel<<<BB * NGRP, 1024>>>(x, gnw, gnb, th);

    // 2) fused QKV': Q,K [B,S,C]; V' = t.Wvo^T transposed [B,C,S]
    qkv_mma<<<dim3(12, SS / 128, BB), 256, SMEM>>>(th, wh, wvo, bq, bk, qh, kh, vth);

    // 3) scores = SCALE * q k^T  (fp16 out)
    gemm_h<<<dim3(SS / 128, SS / 128, BB), 256, SMEM>>>(
        qh, kh, nullptr, sc, CC, CC, CC, SS, sSC, sSC, sSS, SCALE_QK);

    // 4) softmax -> P fp16
    softmax_kernel<<<BB * SS, 256>>>(sc, ph);

    // 5) out[b,c,s] = (P.v')[s,c] + b'[c] + x[b,c,s]   (final)
    gemm_pv_final<<<dim3(CC / 128, SS / 128, BB), 256, SMEM>>>(ph, vth, bp, x, out);
}

// round 15
// speedup vs baseline: 1.1267x; 1.1267x over previous
#include <cuda_runtime.h>
#include <cuda_fp16.h>
#include <math.h>
#include <stdint.h>

// ---------------------------------------------------------------------------
// AttnBlock via mma.sync HMMA (base sm_100 target).
// Single-pass fp16 GEMMs, fp32 accum.
// R15: keep R14's algebraic fusion (out = P.(t.(Wo.Wv)^T) + (Wo.bv+bo) —
// softmax rows sum to 1), but fix the prep matvec: R14's bvec_kernel was a
// serial per-thread dot chain costing 73 us; now warp-per-output (~3 us).
// ---------------------------------------------------------------------------

#define BB   32
#define CC   512
#define SS   1024
#define NGRP 32
#define CPG  16
#define SCALE_QK 0.044194173824159216f

typedef __half fp16;

// ------------------------------- scratch ----------------------------------
static __device__ fp16 g_th [(size_t)BB * SS * CC];
static __device__ fp16 g_qh [(size_t)BB * SS * CC];
static __device__ fp16 g_kh [(size_t)BB * SS * CC];
static __device__ fp16 g_vth[(size_t)BB * CC * SS];   // v' transposed [B,C,S]
static __device__ fp16 g_sc [(size_t)BB * SS * SS];   // fp16 scores
static __device__ fp16 g_ph [(size_t)BB * SS * SS];
static __device__ fp16 g_wh [4 * CC * CC];            // Wq, Wk, Wv, Wo (fp16)
static __device__ fp16 g_wvt[CC * CC];                // Wv^T fp16
static __device__ fp16 g_wvo[CC * CC];                // Wvo = Wo.Wv fp16
static __device__ float g_bp [CC];                    // b' = Wo.bv + bo

// ------------------------------ asm helpers --------------------------------
__device__ __forceinline__ uint32_t smem_u32(const void* p) {
    uint32_t a;
    asm("{ .reg .u64 t; cvta.to.shared.u64 t, %1; cvt.u32.u64 %0, t; }" : "=r"(a) : "l"(p));
    return a;
}
#define CP16(dst, src) \
    asm volatile("cp.async.cg.shared.global [%0], [%1], 16;" :: "r"(dst), "l"(src))
#define CP_COMMIT() asm volatile("cp.async.commit_group;" ::: "memory")
#define CP_WAIT(n)  asm volatile("cp.async.wait_group %0;" :: "n"(n) : "memory")

#define LDSM4(r0, r1, r2, r3, addr) \
    asm volatile("ldmatrix.sync.aligned.m8n8.x4.shared.b16 {%0,%1,%2,%3}, [%4];" \
        : "=r"(r0), "=r"(r1), "=r"(r2), "=r"(r3) : "r"(addr))

#define MMA_FP16(d, a, b) \
    asm volatile("mma.sync.aligned.m16n8k16.row.col.f32.f16.f16.f32 " \
        "{%0,%1,%2,%3}, {%4,%5,%6,%7}, {%8,%9}, {%0,%1,%2,%3};" \
        : "+f"((d)[0]), "+f"((d)[1]), "+f"((d)[2]), "+f"((d)[3]) \
        : "r"((a)[0]), "r"((a)[1]), "r"((a)[2]), "r"((a)[3]), \
          "r"((b)[0]), "r"((b)[1]))

#define STAGE_B 20480

// ---------------------------------------------------------------------------
// Shared GEMM mainloop (128x128 tile, BK=32, 8 warps 4x2, 4-stage cp.async,
// single barrier/chunk, 2 CTAs/SM). Produces acc[2][8][4].
// ---------------------------------------------------------------------------
#define GEMM_MAINLOOP(Aptr, Bptr, bm_, bn_, lda_, ldb_, Kval)                 \
    const uint32_t sb = smem_u32(smem);                                       \
    const int tid = threadIdx.x, wid = tid >> 5, lane = tid & 31;             \
    const int lrow = tid >> 2, lseg = tid & 3;                                \
    float acc[2][8][4];                                                       \
    _Pragma("unroll")                                                         \
    for (int i = 0; i < 2; i++)                                               \
        _Pragma("unroll")                                                     \
        for (int j = 0; j < 8; j++)                                           \
            _Pragma("unroll")                                                 \
            for (int t = 0; t < 4; t++) acc[i][j][t] = 0.f;                   \
    auto load_stage = [&](int k0, int buf) {                                  \
        const uint32_t base = sb + buf * STAGE_B;                             \
        _Pragma("unroll")                                                     \
        for (int half = 0; half < 2; half++) {                                \
            const int r = lrow + half * 64;                                   \
            const uint32_t doff = (uint32_t)(r * 80 + lseg * 16);             \
            CP16(base +         doff, (Aptr) + (size_t)((bm_) + r) * (lda_) + k0 + lseg * 8); \
            CP16(base + 10240 + doff, (Bptr) + (size_t)((bn_) + r) * (ldb_) + k0 + lseg * 8); \
        }                                                                     \
    };                                                                        \
    const int m0 = (wid & 3) * 32, n0 = (wid >> 2) * 64;                      \
    const int arow = (lane & 7) + ((lane >> 3) & 1) * 8;                      \
    const int acol = (lane >> 4) * 8;                                         \
    const int brow = (lane & 7) + (lane >> 4) * 8;                            \
    const int bcol = ((lane >> 3) & 1) * 8;                                   \
    const int NC = (Kval) >> 5;                                               \
    load_stage(0, 0);  CP_COMMIT();                                           \
    load_stage(32, 1); CP_COMMIT();                                           \
    load_stage(64, 2); CP_COMMIT();                                           \
    for (int c = 0; c < NC; c++) {                                            \
        const int rem = NC - 1 - c;                                           \
        if (rem >= 2)      { CP_WAIT(2); }                                    \
        else if (rem == 1) { CP_WAIT(1); }                                    \
        else               { CP_WAIT(0); }                                    \
        __syncthreads();                                                      \
        if (c + 3 < NC) { load_stage((c + 3) << 5, (c + 3) & 3); CP_COMMIT(); } \
        const uint32_t st = sb + (c & 3) * STAGE_B;                           \
        _Pragma("unroll")                                                     \
        for (int kx = 0; kx < 32; kx += 16) {                                 \
            uint32_t fa[2][4];                                                \
            uint32_t fb[8][2];                                                \
            _Pragma("unroll")                                                 \
            for (int mt = 0; mt < 2; mt++) {                                  \
                const uint32_t ad = st +                                      \
                    (uint32_t)(((m0 + mt * 16 + arow) * 40 + kx + acol) * 2); \
                LDSM4(fa[mt][0], fa[mt][1], fa[mt][2], fa[mt][3], ad);        \
            }                                                                 \
            _Pragma("unroll")                                                 \
            for (int p = 0; p < 4; p++) {                                     \
                const uint32_t bd = st + 10240 +                              \
                    (uint32_t)(((n0 + p * 16 + brow) * 40 + kx + bcol) * 2);  \
                LDSM4(fb[2*p][0], fb[2*p][1], fb[2*p+1][0], fb[2*p+1][1], bd);\
            }                                                                 \
            _Pragma("unroll")                                                 \
            for (int mt = 0; mt < 2; mt++)                                    \
                _Pragma("unroll")                                             \
                for (int nt = 0; nt < 8; nt++)                                \
                    MMA_FP16(acc[mt][nt], fa[mt], fb[nt]);                    \
        }                                                                     \
    }                                                                         \
    __syncthreads();

// Normal fp16 epilogue (C[m,n])
#define EPI_FP16(Ch, bias_, bm_, bn_, ldc_, sC_, alpha_)                      \
    _Pragma("unroll")                                                         \
    for (int mt = 0; mt < 2; mt++) {                                          \
        const int gm = (bm_) + m0 + mt * 16 + (lane >> 2);                    \
        _Pragma("unroll")                                                     \
        for (int nt = 0; nt < 8; nt++) {                                      \
            const int gn = (bn_) + n0 + nt * 8 + 2 * (lane & 3);              \
            const float b0 = (bias_) ? (bias_)[gn]     : 0.f;                 \
            const float b1 = (bias_) ? (bias_)[gn + 1] : 0.f;                 \
            const float* d = acc[mt][nt];                                     \
            const size_t r0 = (size_t)blockIdx.z * (sC_) + (size_t)gm * (ldc_) + gn; \
            const size_t r1 = r0 + (size_t)8 * (ldc_);                        \
            *reinterpret_cast<__half2*>(&(Ch)[r0]) = __halves2half2(          \
                __float2half(d[0] * (alpha_) + b0), __float2half(d[1] * (alpha_) + b1)); \
            *reinterpret_cast<__half2*>(&(Ch)[r1]) = __halves2half2(          \
                __float2half(d[2] * (alpha_) + b0), __float2half(d[3] * (alpha_) + b1)); \
        }                                                                     \
    }

// Transposed epilogue via smem stage: writes C^T[n,m] (fp16) or fp32+resid
#define EPI_TRANS(IS_F32, Ch, Cf, bias_, resid_, bm_, bn_, ldc_, sC_, alpha_) \
    {                                                                         \
    float* smt = reinterpret_cast<float*>(smem);                              \
    const int nhme = wid >> 2;                                                \
    _Pragma("unroll")                                                         \
    for (int nh = 0; nh < 2; nh++) {                                          \
        __syncthreads();                                                      \
        if (nhme == nh) {                                                     \
            _Pragma("unroll")                                                 \
            for (int mt = 0; mt < 2; mt++) {                                  \
                const int sl = m0 + mt * 16 + (lane >> 2);                    \
                _Pragma("unroll")                                             \
                for (int nt = 0; nt < 8; nt++) {                              \
                    const int cl = nt * 8 + 2 * (lane & 3);                   \
                    const float b0 = (bias_) ? (bias_)[(bn_) + nh * 64 + cl]     : 0.f; \
                    const float b1 = (bias_) ? (bias_)[(bn_) + nh * 64 + cl + 1] : 0.f; \
                    const float* d = acc[mt][nt];                             \
                    smt[cl       * 132 + sl]     = d[0] * (alpha_) + b0;      \
                    smt[(cl + 1) * 132 + sl]     = d[1] * (alpha_) + b1;      \
                    smt[cl       * 132 + sl + 8] = d[2] * (alpha_) + b0;      \
                    smt[(cl + 1) * 132 + sl + 8] = d[3] * (alpha_) + b1;      \
                }                                                             \
            }                                                                 \
        }                                                                     \
        __syncthreads();                                                      \
        if (!(IS_F32)) {                                                      \
            _Pragma("unroll")                                                 \
            for (int it = 0; it < 16; it++) {                                 \
                const int idx = tid + it * 256;                               \
                const int cl = idx >> 6, s2 = (idx & 63) * 2;                 \
                const size_t o = (size_t)blockIdx.z * (sC_) +                 \
                    (size_t)((bn_) + nh * 64 + cl) * (ldc_) + (bm_) + s2;     \
                *reinterpret_cast<__half2*>(&(Ch)[o]) = __halves2half2(       \
                    __float2half(smt[cl * 132 + s2]),                         \
                    __float2half(smt[cl * 132 + s2 + 1]));                    \
            }                                                                 \
        } else {                                                              \
            _Pragma("unroll")                                                 \
            for (int it = 0; it < 32; it++) {                                 \
                const int idx = tid + it * 256;                               \
                const int cl = idx >> 7, sl = idx & 127;                      \
                const size_t o = (size_t)blockIdx.z * (sC_) +                 \
                    (size_t)((bn_) + nh * 64 + cl) * (ldc_) + (bm_) + sl;     \
                (Cf)[o] = smt[cl * 132 + sl] + (resid_)[o];                   \
            }                                                                 \
        }                                                                     \
    }                                                                         \
    }

// ---------------------------------------------------------------------------
// Fused QKV: grid.x in [0,12): sel = x>>2 picks Q/K/V', bn = (x&3)*128.
// Q,K -> fp16 [B,S,C]; V' = t.Wvo^T -> transposed fp16 [B,C,S], no bias.
// ---------------------------------------------------------------------------
__global__ void __launch_bounds__(256, 2)
qkv_mma(const fp16* __restrict__ T, const fp16* __restrict__ W,
        const fp16* __restrict__ Wvo,
        const float* __restrict__ bq, const float* __restrict__ bk,
        fp16* __restrict__ Q, fp16* __restrict__ Kout, fp16* __restrict__ VT)
{
    extern __shared__ __align__(16) char smem[];
    const int sel = blockIdx.x >> 2;
    const int bm = blockIdx.y * 128, bn = (blockIdx.x & 3) * 128;
    const fp16* A = T + (size_t)blockIdx.z * SS * CC;
    const fp16* B = (sel < 2) ? (W + (size_t)sel * CC * CC) : Wvo;

    GEMM_MAINLOOP(A, B, bm, bn, CC, CC, CC)

    const long long sSC = (long long)SS * CC;
    if (sel == 0) {
        EPI_FP16(Q, bq, bm, bn, CC, sSC, 1.f)
    } else if (sel == 1) {
        EPI_FP16(Kout, bk, bm, bn, CC, sSC, 1.f)
    } else {
        EPI_TRANS(false, VT, (float*)nullptr, (const float*)nullptr,
                  (const float*)nullptr, bm, bn, SS, sSC, 1.f)
    }
}

// ---------------------------------------------------------------------------
// Generic GEMM, fp16 out (scores with alpha; Wvo prep)
// ---------------------------------------------------------------------------
__global__ void __launch_bounds__(256, 2)
gemm_h(const fp16* __restrict__ Ain, const fp16* __restrict__ Bin,
       const float* __restrict__ bias, fp16* __restrict__ Ch,
       int K, int lda, int ldb, int ldc,
       long long sA, long long sB, long long sC, float alpha)
{
    extern __shared__ __align__(16) char smem[];
    const int bm = blockIdx.y * 128, bn = blockIdx.x * 128;
    const fp16* A = Ain + (size_t)blockIdx.z * sA;
    const fp16* B = Bin + (size_t)blockIdx.z * sB;

    GEMM_MAINLOOP(A, B, bm, bn, lda, ldb, K)
    EPI_FP16(Ch, bias, bm, bn, ldc, sC, alpha)
}

// ---------------------------------------------------------------------------
// Final PV GEMM: out[b,c,s] = (P . v')[s,c] + b'[c] + x[b,c,s]
// ---------------------------------------------------------------------------
__global__ void __launch_bounds__(256, 2)
gemm_pv_final(const fp16* __restrict__ P, const fp16* __restrict__ VT,
              const float* __restrict__ bp, const float* __restrict__ X,
              float* __restrict__ Out)
{
    extern __shared__ __align__(16) char smem[];
    const int bm = blockIdx.y * 128, bn = blockIdx.x * 128;
    const fp16* A = P  + (size_t)blockIdx.z * SS * SS;
    const fp16* B = VT + (size_t)blockIdx.z * CC * SS;

    GEMM_MAINLOOP(A, B, bm, bn, SS, SS, SS)

    const long long sCS = (long long)CC * SS;
    EPI_TRANS(true, (fp16*)nullptr, Out, bp, X, bm, bn, SS, sCS, 1.f)
}

// ---------------------------------------------------------------------------
// Fused GroupNorm: one block per (b,g); 1024 threads (one per s), 16 c each.
// ---------------------------------------------------------------------------
__global__ __launch_bounds__(1024)
void gn_fused_kernel(const float* __restrict__ x, const float* __restrict__ w,
                     const float* __restrict__ bgn, fp16* __restrict__ th)
{
    const int b = blockIdx.x >> 5, g = blockIdx.x & 31;
    const size_t base = ((size_t)b * CC + (size_t)g * CPG) * SS;
    const int t = threadIdx.x;

    float v[CPG];
    float s = 0.f, s2 = 0.f;
    #pragma unroll
    for (int c = 0; c < CPG; c++) {
        v[c] = x[base + (size_t)c * SS + t];
        s += v[c]; s2 += v[c] * v[c];
    }
    #pragma unroll
    for (int o = 16; o; o >>= 1) {
        s  += __shfl_xor_sync(0xffffffffu, s, o);
        s2 += __shfl_xor_sync(0xffffffffu, s2, o);
    }
    __shared__ float ws[32], ws2[32];
    __shared__ float s_mu, s_inv;
    const int lane = t & 31, wrp = t >> 5;
    if (lane == 0) { ws[wrp] = s; ws2[wrp] = s2; }
    __syncthreads();
    if (wrp == 0) {
        float a = ws[lane], a2 = ws2[lane];
        #pragma unroll
        for (int o = 16; o; o >>= 1) {
            a  += __shfl_xor_sync(0xffffffffu, a, o);
            a2 += __shfl_xor_sync(0xffffffffu, a2, o);
        }
        if (lane == 0) {
            const float inv_n = 1.f / (CPG * SS);
            const float mu = a * inv_n;
            s_mu = mu;
            s_inv = rsqrtf(a2 * inv_n - mu * mu + 1e-6f);
        }
    }
    __syncthreads();
    const float mu = s_mu, inv = s_inv;

    __half2 o8[CPG / 2];
    #pragma unroll
    for (int c = 0; c < CPG; c += 2) {
        const int cc0 = g * CPG + c;
        o8[c / 2] = __halves2half2(
            __float2half((v[c]     - mu) * inv * w[cc0]     + bgn[cc0]),
            __float2half((v[c + 1] - mu) * inv * w[cc0 + 1] + bgn[cc0 + 1]));
    }
    fp16* dst = th + ((size_t)b * SS + t) * CC + g * CPG;
    reinterpret_cast<uint4*>(dst)[0] = reinterpret_cast<uint4*>(o8)[0];
    reinterpret_cast<uint4*>(dst)[1] = reinterpret_cast<uint4*>(o8)[1];
}

// ---------------------------------------------------------------------------
// Row softmax over 1024 fp16 logits; P -> fp16
// ---------------------------------------------------------------------------
__global__ __launch_bounds__(256)
void softmax_kernel(const fp16* __restrict__ s, fp16* __restrict__ ph)
{
    const size_t ro = (size_t)blockIdx.x * SS;
    const __half2 h0 = reinterpret_cast<const __half2*>(&s[ro])[threadIdx.x * 2];
    const __half2 h1 = reinterpret_cast<const __half2*>(&s[ro])[threadIdx.x * 2 + 1];
    float4 v = make_float4(__low2float(h0), __high2float(h0),
                           __low2float(h1), __high2float(h1));

    float m = fmaxf(fmaxf(v.x, v.y), fmaxf(v.z, v.w));
    #pragma unroll
    for (int o = 16; o; o >>= 1) m = fmaxf(m, __shfl_xor_sync(0xffffffffu, m, o));
    __shared__ float redm[8], reds[8];
    const int lane = threadIdx.x & 31, wid = threadIdx.x >> 5;
    if (lane == 0) redm[wid] = m;
    __syncthreads();
    float M = redm[0];
    #pragma unroll
    for (int i = 1; i < 8; i++) M = fmaxf(M, redm[i]);

    v.x = expf(v.x - M); v.y = expf(v.y - M);
    v.z = expf(v.z - M); v.w = expf(v.w - M);
    float sum = v.x + v.y + v.z + v.w;
    #pragma unroll
    for (int o = 16; o; o >>= 1) sum += __shfl_xor_sync(0xffffffffu, sum, o);
    if (lane == 0) reds[wid] = sum;
    __syncthreads();
    float T = 0.f;
    #pragma unroll
    for (int i = 0; i < 8; i++) T += reds[i];
    const float inv = 1.f / T;

    *reinterpret_cast<__half2*>(&ph[ro + threadIdx.x * 4]) =
        __halves2half2(__float2half(v.x * inv), __float2half(v.y * inv));
    *reinterpret_cast<__half2*>(&ph[ro + threadIdx.x * 4 + 2]) =
        __halves2half2(__float2half(v.z * inv), __float2half(v.w * inv));
}

// ---------------------------------------------------------------------------
// All four weight converts in one launch
// ---------------------------------------------------------------------------
__global__ __launch_bounds__(256)
void wconv4_kernel(const float* __restrict__ a, const float* __restrict__ b,
                   const float* __restrict__ c, const float* __restrict__ d,
                   fp16* __restrict__ dst)
{
    const int n2 = CC * CC / 2;
    for (int i = blockIdx.x * 256 + threadIdx.x; i < n2; i += gridDim.x * 256) {
        const float2 va = reinterpret_cast<const float2*>(a)[i];
        const float2 vb = reinterpret_cast<const float2*>(b)[i];
        const float2 vc = reinterpret_cast<const float2*>(c)[i];
        const float2 vd = reinterpret_cast<const float2*>(d)[i];
        reinterpret_cast<__half2*>(dst)[i]          = __floats2half2_rn(va.x, va.y);
        reinterpret_cast<__half2*>(dst)[n2 + i]     = __floats2half2_rn(vb.x, vb.y);
        reinterpret_cast<__half2*>(dst)[2 * n2 + i] = __floats2half2_rn(vc.x, vc.y);
        reinterpret_cast<__half2*>(dst)[3 * n2 + i] = __floats2half2_rn(vd.x, vd.y);
    }
}

// ---------------------------------------------------------------------------
// Wv fp16 [C,C] -> Wv^T fp16 (32x32 smem tiles)
// ---------------------------------------------------------------------------
__global__ __launch_bounds__(256)
void wtrans_kernel(const fp16* __restrict__ src, fp16* __restrict__ dst)
{
    __shared__ fp16 t[32][33];
    const int r0 = blockIdx.y * 32, c0 = blockIdx.x * 32;
    const int tx = threadIdx.x, ty = threadIdx.y;
    #pragma unroll
    for (int i = ty; i < 32; i += 8)
        t[i][tx] = src[(size_t)(r0 + i) * CC + c0 + tx];
    __syncthreads();
    #pragma unroll
    for (int i = ty; i < 32; i += 8)
        dst[(size_t)(c0 + i) * CC + r0 + tx] = t[tx][i];
}

// ---------------------------------------------------------------------------
// b'[c] = dot(Wo[c,:], bv) + bo[c]  — one WARP per output c (R14's serial
// per-thread version cost 73 us of DRAM-latency chain).
// ---------------------------------------------------------------------------
__global__ __launch_bounds__(256)
void bvec_kernel(const float* __restrict__ Wo, const float* __restrict__ bv,
                 const float* __restrict__ bo, float* __restrict__ bp)
{
    const int c = (blockIdx.x * 256 + threadIdx.x) >> 5;   // warp index = output c
    const int lane = threadIdx.x & 31;
    if (c < CC) {
        float a = 0.f;
        #pragma unroll 4
        for (int j = lane; j < CC; j += 32)
            a += Wo[(size_t)c * CC + j] * bv[j];
        #pragma unroll
        for (int o = 16; o; o >>= 1) a += __shfl_xor_sync(0xffffffffu, a, o);
        if (lane == 0) bp[c] = a + bo[c];
    }
}

// ---------------------------------------------------------------------------
// Launch
// ---------------------------------------------------------------------------
extern "C" void kernel_launch(void* const* d_in, const int* in_sizes, int n_in,
                              void* d_out, int out_size)
{
    const float* x   = (const float*)d_in[0];
    const float* gnw = (const float*)d_in[1];
    const float* gnb = (const float*)d_in[2];
    const float* Wq  = (const float*)d_in[3];
    const float* bq  = (const float*)d_in[4];
    const float* Wk  = (const float*)d_in[5];
    const float* bk  = (const float*)d_in[6];
    const float* Wv  = (const float*)d_in[7];
    const float* bv  = (const float*)d_in[8];
    const float* Wo  = (const float*)d_in[9];
    const float* bo  = (const float*)d_in[10];
    float* out = (float*)d_out;

    fp16 *th, *qh, *kh, *vth, *sc, *ph, *wh, *wvt, *wvo;
    float *bp;
    cudaGetSymbolAddress((void**)&th,  g_th);
    cudaGetSymbolAddress((void**)&qh,  g_qh);
    cudaGetSymbolAddress((void**)&kh,  g_kh);
    cudaGetSymbolAddress((void**)&vth, g_vth);
    cudaGetSymbolAddress((void**)&sc,  g_sc);
    cudaGetSymbolAddress((void**)&ph,  g_ph);
    cudaGetSymbolAddress((void**)&wh,  g_wh);
    cudaGetSymbolAddress((void**)&wvt, g_wvt);
    cudaGetSymbolAddress((void**)&wvo, g_wvo);
    cudaGetSymbolAddress((void**)&bp,  g_bp);

    const int SMEM = 4 * STAGE_B;   // 81920 B
    cudaFuncSetAttribute(qkv_mma,       cudaFuncAttributeMaxDynamicSharedMemorySize, SMEM);
    cudaFuncSetAttribute(gemm_h,        cudaFuncAttributeMaxDynamicSharedMemorySize, SMEM);
    cudaFuncSetAttribute(gemm_pv_final, cudaFuncAttributeMaxDynamicSharedMemorySize, SMEM);

    const long long sSC = (long long)SS * CC;
    const long long sSS = (long long)SS * SS;

    // 0) weight preps: fp16 converts; b'; Wv^T; Wvo = Wo.Wv
    wconv4_kernel<<<256, 256>>>(Wq, Wk, Wv, Wo, wh);
    bvec_kernel<<<64, 256>>>(Wo, bv, bo, bp);
    wtrans_kernel<<<dim3(16, 16), dim3(32, 8)>>>(wh + 2 * CC * CC, wvt);
    // Wvo[c,k] = Wo[c,:] . WvT[k,:]  (A = Wo fp16, B = Wv^T fp16)
    gemm_h<<<dim3(4, 4, 1), 256, SMEM>>>(wh + 3 * CC * CC, wvt, nullptr, wvo,
                                         CC, CC, CC, CC, 0, 0, 0, 1.f);

    // 1) fused GroupNorm -> t [B,S,C] fp16
    gn_fused_kernel<<<BB * NGRP, 1024>>>(x, gnw, gnb, th);

    // 2) fused QKV': Q,K [B,S,C]; V' = t.Wvo^T transposed [B,C,S]
    qkv_mma<<<dim3(12, SS / 128, BB), 256, SMEM>>>(th, wh, wvo, bq, bk, qh, kh, vth);

    // 3) scores = SCALE * q k^T  (fp16 out)
    gemm_h<<<dim3(SS / 128, SS / 128, BB), 256, SMEM>>>(
        qh, kh, nullptr, sc, CC, CC, CC, SS, sSC, sSC, sSS, SCALE_QK);

    // 4) softmax -> P fp16
    softmax_kernel<<<BB * SS, 256>>>(sc, ph);

    // 5) out[b,c,s] = (P.v')[s,c] + b'[c] + x[b,c,s]   (final)
    gemm_pv_final<<<dim3(CC / 128, SS / 128, BB), 256, SMEM>>>(ph, vth, bp, x, out);
}

// round 17
// speedup vs baseline: 1.1433x; 1.0147x over previous
#include <cuda_runtime.h>
#include <cuda_fp16.h>
#include <math.h>
#include <stdint.h>

// ---------------------------------------------------------------------------
// AttnBlock via mma.sync HMMA (base sm_100 target).
// Single-pass fp16 GEMMs, fp32 accum. Wvo algebraic fusion (softmax rows
// sum to 1): out = P.(t.(Wo.Wv)^T) + (Wo.bv + bo).
// R16: ALL independent prep work (Wq/Wk convert, Wo convert, Wv^T from fp32,
// b' matvec) merged INTO the GroupNorm launch as extra blocks — the serial
// prep chain (~12us of tiny launches) now runs concurrently with gn.
// ---------------------------------------------------------------------------

#define BB   32
#define CC   512
#define SS   1024
#define NGRP 32
#define CPG  16
#define SCALE_QK 0.044194173824159216f

typedef __half fp16;

// ------------------------------- scratch ----------------------------------
static __device__ fp16 g_th [(size_t)BB * SS * CC];
static __device__ fp16 g_qh [(size_t)BB * SS * CC];
static __device__ fp16 g_kh [(size_t)BB * SS * CC];
static __device__ fp16 g_vth[(size_t)BB * CC * SS];   // v' transposed [B,C,S]
static __device__ fp16 g_sc [(size_t)BB * SS * SS];   // fp16 scores
static __device__ fp16 g_ph [(size_t)BB * SS * SS];
static __device__ fp16 g_whqk[2 * CC * CC];           // Wq, Wk fp16
static __device__ fp16 g_woh [CC * CC];               // Wo fp16
static __device__ fp16 g_wvt [CC * CC];               // Wv^T fp16
static __device__ fp16 g_wvo [CC * CC];               // Wvo = Wo.Wv fp16
static __device__ float g_bp [CC];                    // b' = Wo.bv + bo

// ------------------------------ asm helpers --------------------------------
__device__ __forceinline__ uint32_t smem_u32(const void* p) {
    uint32_t a;
    asm("{ .reg .u64 t; cvta.to.shared.u64 t, %1; cvt.u32.u64 %0, t; }" : "=r"(a) : "l"(p));
    return a;
}
#define CP16(dst, src) \
    asm volatile("cp.async.cg.shared.global [%0], [%1], 16;" :: "r"(dst), "l"(src))
#define CP_COMMIT() asm volatile("cp.async.commit_group;" ::: "memory")
#define CP_WAIT(n)  asm volatile("cp.async.wait_group %0;" :: "n"(n) : "memory")

#define LDSM4(r0, r1, r2, r3, addr) \
    asm volatile("ldmatrix.sync.aligned.m8n8.x4.shared.b16 {%0,%1,%2,%3}, [%4];" \
        : "=r"(r0), "=r"(r1), "=r"(r2), "=r"(r3) : "r"(addr))

#define MMA_FP16(d, a, b) \
    asm volatile("mma.sync.aligned.m16n8k16.row.col.f32.f16.f16.f32 " \
        "{%0,%1,%2,%3}, {%4,%5,%6,%7}, {%8,%9}, {%0,%1,%2,%3};" \
        : "+f"((d)[0]), "+f"((d)[1]), "+f"((d)[2]), "+f"((d)[3]) \
        : "r"((a)[0]), "r"((a)[1]), "r"((a)[2]), "r"((a)[3]), \
          "r"((b)[0]), "r"((b)[1]))

#define STAGE_B 20480

// ---------------------------------------------------------------------------
// Shared GEMM mainloop (128x128 tile, BK=32, 8 warps 4x2, 4-stage cp.async,
// single barrier/chunk, 2 CTAs/SM). Produces acc[2][8][4].
// ---------------------------------------------------------------------------
#define GEMM_MAINLOOP(Aptr, Bptr, bm_, bn_, lda_, ldb_, Kval)                 \
    const uint32_t sb = smem_u32(smem);                                       \
    const int tid = threadIdx.x, wid = tid >> 5, lane = tid & 31;             \
    const int lrow = tid >> 2, lseg = tid & 3;                                \
    float acc[2][8][4];                                                       \
    _Pragma("unroll")                                                         \
    for (int i = 0; i < 2; i++)                                               \
        _Pragma("unroll")                                                     \
        for (int j = 0; j < 8; j++)                                           \
            _Pragma("unroll")                                                 \
            for (int t = 0; t < 4; t++) acc[i][j][t] = 0.f;                   \
    auto load_stage = [&](int k0, int buf) {                                  \
        const uint32_t base = sb + buf * STAGE_B;                             \
        _Pragma("unroll")                                                     \
        for (int half = 0; half < 2; half++) {                                \
            const int r = lrow + half * 64;                                   \
            const uint32_t doff = (uint32_t)(r * 80 + lseg * 16);             \
            CP16(base +         doff, (Aptr) + (size_t)((bm_) + r) * (lda_) + k0 + lseg * 8); \
            CP16(base + 10240 + doff, (Bptr) + (size_t)((bn_) + r) * (ldb_) + k0 + lseg * 8); \
        }                                                                     \
    };                                                                        \
    const int m0 = (wid & 3) * 32, n0 = (wid >> 2) * 64;                      \
    const int arow = (lane & 7) + ((lane >> 3) & 1) * 8;                      \
    const int acol = (lane >> 4) * 8;                                         \
    const int brow = (lane & 7) + (lane >> 4) * 8;                            \
    const int bcol = ((lane >> 3) & 1) * 8;                                   \
    const int NC = (Kval) >> 5;                                               \
    load_stage(0, 0);  CP_COMMIT();                                           \
    load_stage(32, 1); CP_COMMIT();                                           \
    load_stage(64, 2); CP_COMMIT();                                           \
    for (int c = 0; c < NC; c++) {                                            \
        const int rem = NC - 1 - c;                                           \
        if (rem >= 2)      { CP_WAIT(2); }                                    \
        else if (rem == 1) { CP_WAIT(1); }                                    \
        else               { CP_WAIT(0); }                                    \
        __syncthreads();                                                      \
        if (c + 3 < NC) { load_stage((c + 3) << 5, (c + 3) & 3); CP_COMMIT(); } \
        const uint32_t st = sb + (c & 3) * STAGE_B;                           \
        _Pragma("unroll")                                                     \
        for (int kx = 0; kx < 32; kx += 16) {                                 \
            uint32_t fa[2][4];                                                \
            uint32_t fb[8][2];                                                \
            _Pragma("unroll")                                                 \
            for (int mt = 0; mt < 2; mt++) {                                  \
                const uint32_t ad = st +                                      \
                    (uint32_t)(((m0 + mt * 16 + arow) * 40 + kx + acol) * 2); \
                LDSM4(fa[mt][0], fa[mt][1], fa[mt][2], fa[mt][3], ad);        \
            }                                                                 \
            _Pragma("unroll")                                                 \
            for (int p = 0; p < 4; p++) {                                     \
                const uint32_t bd = st + 10240 +                              \
                    (uint32_t)(((n0 + p * 16 + brow) * 40 + kx + bcol) * 2);  \
                LDSM4(fb[2*p][0], fb[2*p][1], fb[2*p+1][0], fb[2*p+1][1], bd);\
            }                                                                 \
            _Pragma("unroll")                                                 \
            for (int mt = 0; mt < 2; mt++)                                    \
                _Pragma("unroll")                                             \
                for (int nt = 0; nt < 8; nt++)                                \
                    MMA_FP16(acc[mt][nt], fa[mt], fb[nt]);                    \
        }                                                                     \
    }                                                                         \
    __syncthreads();

// Normal fp16 epilogue (C[m,n])
#define EPI_FP16(Ch, bias_, bm_, bn_, ldc_, sC_, alpha_)                      \
    _Pragma("unroll")                                                         \
    for (int mt = 0; mt < 2; mt++) {                                          \
        const int gm = (bm_) + m0 + mt * 16 + (lane >> 2);                    \
        _Pragma("unroll")                                                     \
        for (int nt = 0; nt < 8; nt++) {                                      \
            const int gn = (bn_) + n0 + nt * 8 + 2 * (lane & 3);              \
            const float b0 = (bias_) ? (bias_)[gn]     : 0.f;                 \
            const float b1 = (bias_) ? (bias_)[gn + 1] : 0.f;                 \
            const float* d = acc[mt][nt];                                     \
            const size_t r0 = (size_t)blockIdx.z * (sC_) + (size_t)gm * (ldc_) + gn; \
            const size_t r1 = r0 + (size_t)8 * (ldc_);                        \
            *reinterpret_cast<__half2*>(&(Ch)[r0]) = __halves2half2(          \
                __float2half(d[0] * (alpha_) + b0), __float2half(d[1] * (alpha_) + b1)); \
            *reinterpret_cast<__half2*>(&(Ch)[r1]) = __halves2half2(          \
                __float2half(d[2] * (alpha_) + b0), __float2half(d[3] * (alpha_) + b1)); \
        }                                                                     \
    }

// Transposed epilogue via smem stage: writes C^T[n,m] (fp16) or fp32+resid
#define EPI_TRANS(IS_F32, Ch, Cf, bias_, resid_, bm_, bn_, ldc_, sC_, alpha_) \
    {                                                                         \
    float* smt = reinterpret_cast<float*>(smem);                              \
    const int nhme = wid >> 2;                                                \
    _Pragma("unroll")                                                         \
    for (int nh = 0; nh < 2; nh++) {                                          \
        __syncthreads();                                                      \
        if (nhme == nh) {                                                     \
            _Pragma("unroll")                                                 \
            for (int mt = 0; mt < 2; mt++) {                                  \
                const int sl = m0 + mt * 16 + (lane >> 2);                    \
                _Pragma("unroll")                                             \
                for (int nt = 0; nt < 8; nt++) {                              \
                    const int cl = nt * 8 + 2 * (lane & 3);                   \
                    const float b0 = (bias_) ? (bias_)[(bn_) + nh * 64 + cl]     : 0.f; \
                    const float b1 = (bias_) ? (bias_)[(bn_) + nh * 64 + cl + 1] : 0.f; \
                    const float* d = acc[mt][nt];                             \
                    smt[cl       * 132 + sl]     = d[0] * (alpha_) + b0;      \
                    smt[(cl + 1) * 132 + sl]     = d[1] * (alpha_) + b1;      \
                    smt[cl       * 132 + sl + 8] = d[2] * (alpha_) + b0;      \
                    smt[(cl + 1) * 132 + sl + 8] = d[3] * (alpha_) + b1;      \
                }                                                             \
            }                                                                 \
        }                                                                     \
        __syncthreads();                                                      \
        if (!(IS_F32)) {                                                      \
            _Pragma("unroll")                                                 \
            for (int it = 0; it < 16; it++) {                                 \
                const int idx = tid + it * 256;                               \
                const int cl = idx >> 6, s2 = (idx & 63) * 2;                 \
                const size_t o = (size_t)blockIdx.z * (sC_) +                 \
                    (size_t)((bn_) + nh * 64 + cl) * (ldc_) + (bm_) + s2;     \
                *reinterpret_cast<__half2*>(&(Ch)[o]) = __halves2half2(       \
                    __float2half(smt[cl * 132 + s2]),                         \
                    __float2half(smt[cl * 132 + s2 + 1]));                    \
            }                                                                 \
        } else {                                                              \
            _Pragma("unroll")                                                 \
            for (int it = 0; it < 32; it++) {                                 \
                const int idx = tid + it * 256;                               \
                const int cl = idx >> 7, sl = idx & 127;                      \
                const size_t o = (size_t)blockIdx.z * (sC_) +                 \
                    (size_t)((bn_) + nh * 64 + cl) * (ldc_) + (bm_) + sl;     \
                (Cf)[o] = smt[cl * 132 + sl] + (resid_)[o];                   \
            }                                                                 \
        }                                                                     \
    }                                                                         \
    }

// ---------------------------------------------------------------------------
// Fused QKV: grid.x in [0,12): sel = x>>2 picks Q/K/V', bn = (x&3)*128.
// Q,K -> fp16 [B,S,C]; V' = t.Wvo^T -> transposed fp16 [B,C,S], no bias.
// ---------------------------------------------------------------------------
__global__ void __launch_bounds__(256, 2)
qkv_mma(const fp16* __restrict__ T, const fp16* __restrict__ Wqk,
        const fp16* __restrict__ Wvo,
        const float* __restrict__ bq, const float* __restrict__ bk,
        fp16* __restrict__ Q, fp16* __restrict__ Kout, fp16* __restrict__ VT)
{
    extern __shared__ __align__(16) char smem[];
    const int sel = blockIdx.x >> 2;
    const int bm = blockIdx.y * 128, bn = (blockIdx.x & 3) * 128;
    const fp16* A = T + (size_t)blockIdx.z * SS * CC;
    const fp16* B = (sel < 2) ? (Wqk + (size_t)sel * CC * CC) : Wvo;

    GEMM_MAINLOOP(A, B, bm, bn, CC, CC, CC)

    const long long sSC = (long long)SS * CC;
    if (sel == 0) {
        EPI_FP16(Q, bq, bm, bn, CC, sSC, 1.f)
    } else if (sel == 1) {
        EPI_FP16(Kout, bk, bm, bn, CC, sSC, 1.f)
    } else {
        EPI_TRANS(false, VT, (float*)nullptr, (const float*)nullptr,
                  (const float*)nullptr, bm, bn, SS, sSC, 1.f)
    }
}

// ---------------------------------------------------------------------------
// Generic GEMM, fp16 out (scores with alpha; Wvo prep)
// ---------------------------------------------------------------------------
__global__ void __launch_bounds__(256, 2)
gemm_h(const fp16* __restrict__ Ain, const fp16* __restrict__ Bin,
       const float* __restrict__ bias, fp16* __restrict__ Ch,
       int K, int lda, int ldb, int ldc,
       long long sA, long long sB, long long sC, float alpha)
{
    extern __shared__ __align__(16) char smem[];
    const int bm = blockIdx.y * 128, bn = blockIdx.x * 128;
    const fp16* A = Ain + (size_t)blockIdx.z * sA;
    const fp16* B = Bin + (size_t)blockIdx.z * sB;

    GEMM_MAINLOOP(A, B, bm, bn, lda, ldb, K)
    EPI_FP16(Ch, bias, bm, bn, ldc, sC, alpha)
}

// ---------------------------------------------------------------------------
// Final PV GEMM: out[b,c,s] = (P . v')[s,c] + b'[c] + x[b,c,s]
// ---------------------------------------------------------------------------
__global__ void __launch_bounds__(256, 2)
gemm_pv_final(const fp16* __restrict__ P, const fp16* __restrict__ VT,
              const float* __restrict__ bp, const float* __restrict__ X,
              float* __restrict__ Out)
{
    extern __shared__ __align__(16) char smem[];
    const int bm = blockIdx.y * 128, bn = blockIdx.x * 128;
    const fp16* A = P  + (size_t)blockIdx.z * SS * SS;
    const fp16* B = VT + (size_t)blockIdx.z * CC * SS;

    GEMM_MAINLOOP(A, B, bm, bn, SS, SS, SS)

    const long long sCS = (long long)CC * SS;
    EPI_TRANS(true, (fp16*)nullptr, Out, bp, X, bm, bn, SS, sCS, 1.f)
}

// ---------------------------------------------------------------------------
// Mega-aux kernel (1024 threads):
//   blocks [0,1024):     fused GroupNorm (stats+normalize+transpose -> th)
//   blocks [1024,1040):  Wq,Wk fp32->fp16 converts (16 blocks)
//   blocks [1040,1056):  b'[c] = Wo[c,:].bv + bo[c]  (one warp per c)
//   blocks [1056,1072):  Wo fp32->fp16 convert (16 blocks)
//   blocks [1072,1136):  Wv fp32 -> Wv^T fp16 (64 blocks, 4 32x32 tiles each)
// All branches are independent; per-branch __syncthreads are block-uniform.
// ---------------------------------------------------------------------------
__global__ __launch_bounds__(1024)
void aux_kernel(const float* __restrict__ x, const float* __restrict__ gnw,
                const float* __restrict__ gnb, fp16* __restrict__ th,
                const float* __restrict__ Wq, const float* __restrict__ Wk,
                fp16* __restrict__ whqk,
                const float* __restrict__ Wo, fp16* __restrict__ woh,
                const float* __restrict__ Wv, fp16* __restrict__ wvt,
                const float* __restrict__ bv, const float* __restrict__ bo,
                float* __restrict__ bp)
{
    const int blk = blockIdx.x;
    const int t = threadIdx.x;

    if (blk < 1024) {
        // ---- fused GroupNorm ----
        const int b = blk >> 5, g = blk & 31;
        const size_t base = ((size_t)b * CC + (size_t)g * CPG) * SS;

        float v[CPG];
        float s = 0.f, s2 = 0.f;
        #pragma unroll
        for (int c = 0; c < CPG; c++) {
            v[c] = x[base + (size_t)c * SS + t];
            s += v[c]; s2 += v[c] * v[c];
        }
        #pragma unroll
        for (int o = 16; o; o >>= 1) {
            s  += __shfl_xor_sync(0xffffffffu, s, o);
            s2 += __shfl_xor_sync(0xffffffffu, s2, o);
        }
        __shared__ float ws[32], ws2[32];
        __shared__ float s_mu, s_inv;
        const int lane = t & 31, wrp = t >> 5;
        if (lane == 0) { ws[wrp] = s; ws2[wrp] = s2; }
        __syncthreads();
        if (wrp == 0) {
            float a = ws[lane], a2 = ws2[lane];
            #pragma unroll
            for (int o = 16; o; o >>= 1) {
                a  += __shfl_xor_sync(0xffffffffu, a, o);
                a2 += __shfl_xor_sync(0xffffffffu, a2, o);
            }
            if (lane == 0) {
                const float inv_n = 1.f / (CPG * SS);
                const float mu = a * inv_n;
                s_mu = mu;
                s_inv = rsqrtf(a2 * inv_n - mu * mu + 1e-6f);
            }
        }
        __syncthreads();
        const float mu = s_mu, inv = s_inv;

        __half2 o8[CPG / 2];
        #pragma unroll
        for (int c = 0; c < CPG; c += 2) {
            const int cc0 = g * CPG + c;
            o8[c / 2] = __halves2half2(
                __float2half((v[c]     - mu) * inv * gnw[cc0]     + gnb[cc0]),
                __float2half((v[c + 1] - mu) * inv * gnw[cc0 + 1] + gnb[cc0 + 1]));
        }
        fp16* dst = th + ((size_t)b * SS + t) * CC + g * CPG;
        reinterpret_cast<uint4*>(dst)[0] = reinterpret_cast<uint4*>(o8)[0];
        reinterpret_cast<uint4*>(dst)[1] = reinterpret_cast<uint4*>(o8)[1];
    } else if (blk < 1040) {
        // ---- Wq, Wk converts ----
        const int n2 = CC * CC / 2;                     // half2 count per matrix
        const int i0 = (blk - 1024) * 1024 + t;          // 16384 threads total
        for (int i = i0; i < n2; i += 16 * 1024) {
            const float2 va = reinterpret_cast<const float2*>(Wq)[i];
            const float2 vb = reinterpret_cast<const float2*>(Wk)[i];
            reinterpret_cast<__half2*>(whqk)[i]      = __floats2half2_rn(va.x, va.y);
            reinterpret_cast<__half2*>(whqk)[n2 + i] = __floats2half2_rn(vb.x, vb.y);
        }
    } else if (blk < 1056) {
        // ---- b'[c] = Wo[c,:].bv + bo[c], one warp per c ----
        const int lane = t & 31, wrp = t >> 5;
        const int c = (blk - 1040) * 32 + wrp;           // 512 warps -> 512 outputs
        float a = 0.f;
        #pragma unroll 4
        for (int j = lane; j < CC; j += 32)
            a += Wo[(size_t)c * CC + j] * bv[j];
        #pragma unroll
        for (int o = 16; o; o >>= 1) a += __shfl_xor_sync(0xffffffffu, a, o);
        if (lane == 0) bp[c] = a + bo[c];
    } else if (blk < 1072) {
        // ---- Wo convert ----
        const int n2 = CC * CC / 2;
        const int i0 = (blk - 1056) * 1024 + t;
        for (int i = i0; i < n2; i += 16 * 1024) {
            const float2 v2 = reinterpret_cast<const float2*>(Wo)[i];
            reinterpret_cast<__half2*>(woh)[i] = __floats2half2_rn(v2.x, v2.y);
        }
    } else {
        // ---- Wv fp32 -> Wv^T fp16, 4 tiles of 32x32 per block ----
        __shared__ float tt[32][33];
        const int tx = t & 31, ty = t >> 5;              // 32x32 thread grid
        #pragma unroll
        for (int k = 0; k < 4; k++) {
            const int tile = (blk - 1072) * 4 + k;       // 256 tiles total
            const int r0 = (tile >> 4) * 32, c0 = (tile & 15) * 32;
            tt[ty][tx] = Wv[(size_t)(r0 + ty) * CC + c0 + tx];
            __syncthreads();
            wvt[(size_t)(c0 + ty) * CC + r0 + tx] = __float2half(tt[tx][ty]);
            __syncthreads();
        }
    }
}

// ---------------------------------------------------------------------------
// Row softmax over 1024 fp16 logits; P -> fp16
// ---------------------------------------------------------------------------
__global__ __launch_bounds__(256)
void softmax_kernel(const fp16* __restrict__ s, fp16* __restrict__ ph)
{
    const size_t ro = (size_t)blockIdx.x * SS;
    const __half2 h0 = reinterpret_cast<const __half2*>(&s[ro])[threadIdx.x * 2];
    const __half2 h1 = reinterpret_cast<const __half2*>(&s[ro])[threadIdx.x * 2 + 1];
    float4 v = make_float4(__low2float(h0), __high2float(h0),
                           __low2float(h1), __high2float(h1));

    float m = fmaxf(fmaxf(v.x, v.y), fmaxf(v.z, v.w));
    #pragma unroll
    for (int o = 16; o; o >>= 1) m = fmaxf(m, __shfl_xor_sync(0xffffffffu, m, o));
    __shared__ float redm[8], reds[8];
    const int lane = threadIdx.x & 31, wid = threadIdx.x >> 5;
    if (lane == 0) redm[wid] = m;
    __syncthreads();
    float M = redm[0];
    #pragma unroll
    for (int i = 1; i < 8; i++) M = fmaxf(M, redm[i]);

    v.x = expf(v.x - M); v.y = expf(v.y - M);
    v.z = expf(v.z - M); v.w = expf(v.w - M);
    float sum = v.x + v.y + v.z + v.w;
    #pragma unroll
    for (int o = 16; o; o >>= 1) sum += __shfl_xor_sync(0xffffffffu, sum, o);
    if (lane == 0) reds[wid] = sum;
    __syncthreads();
    float T = 0.f;
    #pragma unroll
    for (int i = 0; i < 8; i++) T += reds[i];
    const float inv = 1.f / T;

    *reinterpret_cast<__half2*>(&ph[ro + threadIdx.x * 4]) =
        __halves2half2(__float2half(v.x * inv), __float2half(v.y * inv));
    *reinterpret_cast<__half2*>(&ph[ro + threadIdx.x * 4 + 2]) =
        __halves2half2(__float2half(v.z * inv), __float2half(v.w * inv));
}

// ---------------------------------------------------------------------------
// Launch
// ---------------------------------------------------------------------------
extern "C" void kernel_launch(void* const* d_in, const int* in_sizes, int n_in,
                              void* d_out, int out_size)
{
    const float* x   = (const float*)d_in[0];
    const float* gnw = (const float*)d_in[1];
    const float* gnb = (const float*)d_in[2];
    const float* Wq  = (const float*)d_in[3];
    const float* bq  = (const float*)d_in[4];
    const float* Wk  = (const float*)d_in[5];
    const float* bk  = (const float*)d_in[6];
    const float* Wv  = (const float*)d_in[7];
    const float* bv  = (const float*)d_in[8];
    const float* Wo  = (const float*)d_in[9];
    const float* bo  = (const float*)d_in[10];
    float* out = (float*)d_out;

    fp16 *th, *qh, *kh, *vth, *sc, *ph, *whqk, *woh, *wvt, *wvo;
    float *bp;
    cudaGetSymbolAddress((void**)&th,   g_th);
    cudaGetSymbolAddress((void**)&qh,   g_qh);
    cudaGetSymbolAddress((void**)&kh,   g_kh);
    cudaGetSymbolAddress((void**)&vth,  g_vth);
    cudaGetSymbolAddress((void**)&sc,   g_sc);
    cudaGetSymbolAddress((void**)&ph,   g_ph);
    cudaGetSymbolAddress((void**)&whqk, g_whqk);
    cudaGetSymbolAddress((void**)&woh,  g_woh);
    cudaGetSymbolAddress((void**)&wvt,  g_wvt);
    cudaGetSymbolAddress((void**)&wvo,  g_wvo);
    cudaGetSymbolAddress((void**)&bp,   g_bp);

    const int SMEM = 4 * STAGE_B;   // 81920 B
    cudaFuncSetAttribute(qkv_mma,       cudaFuncAttributeMaxDynamicSharedMemorySize, SMEM);
    cudaFuncSetAttribute(gemm_h,        cudaFuncAttributeMaxDynamicSharedMemorySize, SMEM);
    cudaFuncSetAttribute(gemm_pv_final, cudaFuncAttributeMaxDynamicSharedMemorySize, SMEM);

    const long long sSC = (long long)SS * CC;
    const long long sSS = (long long)SS * SS;

    // 1) mega-aux: GroupNorm + all weight/bias preps in one launch
    aux_kernel<<<1136, 1024>>>(x, gnw, gnb, th, Wq, Wk, whqk,
                               Wo, woh, Wv, wvt, bv, bo, bp);

    // 2) Wvo = Wo.Wv  (A = Wo fp16, B = Wv^T fp16)
    gemm_h<<<dim3(4, 4, 1), 256, SMEM>>>(woh, wvt, nullptr, wvo,
                                         CC, CC, CC, CC, 0, 0, 0, 1.f);

    // 3) fused QKV': Q,K [B,S,C]; V' = t.Wvo^T transposed [B,C,S]
    qkv_mma<<<dim3(12, SS / 128, BB), 256, SMEM>>>(th, whqk, wvo, bq, bk, qh, kh, vth);

    // 4) scores = SCALE * q k^T  (fp16 out)
    gemm_h<<<dim3(SS / 128, SS / 128, BB), 256, SMEM>>>(
        qh, kh, nullptr, sc, CC, CC, CC, SS, sSC, sSC, sSS, SCALE_QK);

    // 5) softmax -> P fp16
    softmax_kernel<<<BB * SS, 256>>>(sc, ph);

    // 6) out[b,c,s] = (P.v')[s,c] + b'[c] + x[b,c,s]   (final)
    gemm_pv_final<<<dim3(CC / 128, SS / 128, BB), 256, SMEM>>>(ph, vth, bp, x, out);
}